// round 5
// baseline (speedup 1.0000x reference)
#include <cuda_runtime.h>
#include <math.h>

#define PP 3
#define NN 50000
#define EE 256000
#define CC 5
#define FF 68
#define FE 16
#define FN 64
#define F2 (2*FF)   // 136

typedef unsigned long long ull;

#define PACK_F32X2(out, lo, hi) \
    asm("mov.b64 %0, {%1, %2};" : "=l"(out) : "f"(lo), "f"(hi))
#define UNPACK_F32X2(lo, hi, in) \
    asm("mov.b64 {%0, %1}, %2;" : "=f"(lo), "=f"(hi) : "l"(in))
#define FMA_F32X2(d, a, b, c) \
    asm("fma.rn.f32x2 %0, %1, %2, %3;" : "=l"(d) : "l"(a), "l"(b), "l"(c))

__device__ __forceinline__ float tanh_fast(float x) {
    float y; asm("tanh.approx.f32 %0, %1;" : "=f"(y) : "f"(x)); return y;
}

// Scratch: aggr [P,N,C,F] = 204 MB, A/B partials [P,N,C,16] = 48 MB each
__device__ __align__(16) float g_aggr[(size_t)PP*NN*CC*FF];
__device__ __align__(16) float g_A[(size_t)PP*NN*CC*FE];
__device__ __align__(16) float g_B[(size_t)PP*NN*CC*FE];
__device__ int g_is64;

__global__ void detect_kernel(const void* __restrict__ ei) {
    const long long* q = (const long long*)ei;
    int ok = 1;
    for (int i = 0; i < 64; ++i) {
        long long v = q[i];
        if (v < 0 || v >= NN) { ok = 0; break; }
    }
    g_is64 = ok;
}

__global__ void zero_kernel() {
    const size_t total = (size_t)PP*NN*CC*FF/4;
    float4* p = (float4*)g_aggr;
    const float4 z = make_float4(0.f, 0.f, 0.f, 0.f);
    for (size_t i = (size_t)blockIdx.x*blockDim.x + threadIdx.x; i < total;
         i += (size_t)gridDim.x*blockDim.x)
        p[i] = z;
}

__device__ __forceinline__ void red4(float* addr, float a, float b, float c, float d) {
    asm volatile("red.global.add.v4.f32 [%0], {%1,%2,%3,%4};"
                 :: "l"(addr), "f"(a), "f"(b), "f"(c), "f"(d) : "memory");
}

// 16 outputs (8 f32x2 acc) += u * w[0..15]
__device__ __forceinline__ void fma16(ull* acc2, const float* wk, float u) {
    ull uu; PACK_F32X2(uu, u, u);
    const ulonglong2* w = (const ulonglong2*)wk;
    #pragma unroll
    for (int j = 0; j < 4; ++j) {
        ulonglong2 wv = w[j];
        FMA_F32X2(acc2[2*j+0], uu, wv.x, acc2[2*j+0]);
        FMA_F32X2(acc2[2*j+1], uu, wv.y, acc2[2*j+1]);
    }
}

// dual-node: 16 outputs each, shared weight row (1 LDS : 4 FMA2)
__device__ __forceinline__ void fma16_dual(ull* a0, ull* a1, const float* wk,
                                           float u0, float u1) {
    ull uu0, uu1; PACK_F32X2(uu0, u0, u0); PACK_F32X2(uu1, u1, u1);
    const ulonglong2* w = (const ulonglong2*)wk;
    #pragma unroll
    for (int j = 0; j < 4; ++j) {
        ulonglong2 wv = w[j];
        FMA_F32X2(a0[2*j+0], uu0, wv.x, a0[2*j+0]);
        FMA_F32X2(a0[2*j+1], uu0, wv.y, a0[2*j+1]);
        FMA_F32X2(a1[2*j+0], uu1, wv.x, a1[2*j+0]);
        FMA_F32X2(a1[2*j+1], uu1, wv.y, a1[2*j+1]);
    }
}

// dual-node: 64 outputs each, shared weight row
__device__ __forceinline__ void fma64_dual(ull* a0, ull* a1, const float* wk,
                                           float u0, float u1) {
    ull uu0, uu1; PACK_F32X2(uu0, u0, u0); PACK_F32X2(uu1, u1, u1);
    const ulonglong2* w = (const ulonglong2*)wk;
    #pragma unroll
    for (int j = 0; j < 16; ++j) {
        ulonglong2 wv = w[j];
        FMA_F32X2(a0[2*j+0], uu0, wv.x, a0[2*j+0]);
        FMA_F32X2(a0[2*j+1], uu0, wv.y, a0[2*j+1]);
        FMA_F32X2(a1[2*j+0], uu1, wv.x, a1[2*j+0]);
        FMA_F32X2(a1[2*j+1], uu1, wv.y, a1[2*j+1]);
    }
}

// ---------------------------------------------------------------------------
// Precompute kernel: per (node, class), A = W1a.x + b1 and B = W1b.x.
// Weight smem layout [c][k][32]: cols 0..15 = A-weights W[c][g][k],
// cols 16..31 = B-weights W[c][g][68+k]; same input scalar feeds both.
// ---------------------------------------------------------------------------
__global__ __launch_bounds__(256) void pre_kernel(
    const float* __restrict__ x,
    const float* __restrict__ We1, const float* __restrict__ be1)
{
    __shared__ __align__(16) float sW[CC*FF*32];  // 10880 floats = 43.5 KB
    __shared__ float sb1[CC*FE];

    const int p = blockIdx.y;
    for (int i = threadIdx.x; i < CC*FF*32; i += blockDim.x) {
        const int c = i / (FF*32);
        const int r = i % (FF*32);
        const int k = r / 32;
        const int j = r % 32;
        const int g = (j < 16) ? j : j - 16;
        const int kk = (j < 16) ? k : FF + k;
        sW[i] = We1[(((size_t)p*CC + c)*FE + g)*F2 + kk];
    }
    for (int i = threadIdx.x; i < CC*FE; i += blockDim.x)
        sb1[i] = be1[p*CC*FE + i];
    __syncthreads();

    const int idx = blockIdx.x*blockDim.x + threadIdx.x;
    if (idx >= NN*CC) return;
    const int n = idx / CC;
    const int c = idx % CC;

    const float4* x4 = (const float4*)(x + (((size_t)p*NN + n)*CC + c)*FF);

    ull accA[8], accB[8];
    #pragma unroll
    for (int j = 0; j < 8; ++j) {
        PACK_F32X2(accA[j], sb1[c*FE + 2*j], sb1[c*FE + 2*j + 1]);
        float z = 0.f;
        PACK_F32X2(accB[j], z, z);
    }

    const float* wb = sW + c*FF*32;
    #pragma unroll 1
    for (int fc = 0; fc < FF/4; ++fc) {
        const float4 u = x4[fc];
        const float* wk = wb + (4*fc)*32;
        fma16(accA, wk + 0*32,      u.x); fma16(accB, wk + 0*32 + 16, u.x);
        fma16(accA, wk + 1*32,      u.y); fma16(accB, wk + 1*32 + 16, u.y);
        fma16(accA, wk + 2*32,      u.z); fma16(accB, wk + 2*32 + 16, u.z);
        fma16(accA, wk + 3*32,      u.w); fma16(accB, wk + 3*32 + 16, u.w);
    }

    float* Ao = g_A + (((size_t)p*NN + n)*CC + c)*FE;
    float* Bo = g_B + (((size_t)p*NN + n)*CC + c)*FE;
    #pragma unroll
    for (int j = 0; j < 8; j += 2) {
        float a0, a1, a2, a3, b0, b1, b2, b3;
        UNPACK_F32X2(a0, a1, accA[j]);
        UNPACK_F32X2(a2, a3, accA[j+1]);
        UNPACK_F32X2(b0, b1, accB[j]);
        UNPACK_F32X2(b2, b3, accB[j+1]);
        *(float4*)(Ao + 2*j) = make_float4(a0, a1, a2, a3);
        *(float4*)(Bo + 2*j) = make_float4(b0, b1, b2, b3);
    }
}

// ---------------------------------------------------------------------------
// Edge kernel: gather A[dst]+B[src], tanh-gate, class softmax, scatter w*x_j.
// No heavy math left; memory/atomic bound.
// ---------------------------------------------------------------------------
__global__ __launch_bounds__(256) void edge_kernel(
    const float* __restrict__ x, const void* __restrict__ ei,
    const float* __restrict__ We2, const float* __restrict__ be2)
{
    __shared__ float sW2[CC*FE];
    __shared__ float sb2[CC];

    const int p = blockIdx.y;
    for (int i = threadIdx.x; i < CC*FE; i += blockDim.x)
        sW2[i] = We2[p*CC*FE + i];
    if (threadIdx.x < CC) sb2[threadIdx.x] = be2[p*CC + threadIdx.x];
    __syncthreads();

    const int is64 = g_is64;
    const long long* ei64 = (const long long*)ei;
    const int*       ei32 = (const int*)ei;
    const size_t base = (size_t)p*2*EE;

    const int e = blockIdx.x*blockDim.x + threadIdx.x;   // EE % 256 == 0
    int s, d;
    if (is64) {
        s = (int)ei64[base + e];
        d = (int)ei64[base + EE + e];
    } else {
        s = ei32[base + e];
        d = ei32[base + EE + e];
    }

    const float4* Ad = (const float4*)(g_A + ((size_t)p*NN + d)*(CC*FE));
    const float4* Bs = (const float4*)(g_B + ((size_t)p*NN + s)*(CC*FE));

    float lg[CC];
    #pragma unroll
    for (int c = 0; c < CC; ++c) {
        float l = sb2[c];
        #pragma unroll
        for (int j = 0; j < 4; ++j) {
            const float4 a = Ad[c*4 + j];
            const float4 b = Bs[c*4 + j];
            l += tanh_fast(a.x + b.x) * sW2[c*FE + 4*j + 0]
               + tanh_fast(a.y + b.y) * sW2[c*FE + 4*j + 1]
               + tanh_fast(a.z + b.z) * sW2[c*FE + 4*j + 2]
               + tanh_fast(a.w + b.w) * sW2[c*FE + 4*j + 3];
        }
        lg[c] = l;
    }

    float mx = lg[0];
    #pragma unroll
    for (int c = 1; c < CC; ++c) mx = fmaxf(mx, lg[c]);
    float w[CC];
    float sum = 0.f;
    #pragma unroll
    for (int c = 0; c < CC; ++c) { w[c] = expf(lg[c] - mx); sum += w[c]; }
    const float inv = 1.f / sum;

    const float* xj = x + ((size_t)p*NN + s)*(CC*FF);
    float* ap = g_aggr + ((size_t)p*NN + d)*(CC*FF);
    #pragma unroll
    for (int c = 0; c < CC; ++c) {
        const float wc = w[c] * inv;
        const float4* mj = (const float4*)(xj + c*FF);
        float* a = ap + c*FF;
        #pragma unroll 1
        for (int fc = 0; fc < FF/4; ++fc) {
            const float4 v = mj[fc];
            red4(a + 4*fc, wc*v.x, wc*v.y, wc*v.z, wc*v.w);
        }
    }
}

// ---------------------------------------------------------------------------
// Node kernel: 2 nodes per thread, shared weight LDS feeds both (1:4 ratio).
// Block = 128 threads covers 256 nodes of one (plane, class).
// ---------------------------------------------------------------------------
__global__ __launch_bounds__(128) void node_kernel(
    const float* __restrict__ x,
    const float* __restrict__ Wn1, const float* __restrict__ bn1,
    const float* __restrict__ Wn2, const float* __restrict__ bn2,
    float* __restrict__ out)
{
    extern __shared__ __align__(16) float sm[];
    float* sW1t = sm;                  // [k=136][g=64]
    float* sW2t = sm + F2*FN;          // [k=64][g=64]
    float* sb1  = sW2t + FN*FN;
    float* sb2  = sb1 + FN;

    const int c = blockIdx.y;
    const int p = blockIdx.z;
    const size_t wo = (size_t)p*CC + c;
    for (int i = threadIdx.x; i < F2*FN; i += blockDim.x) {
        const int k = i / FN, g = i % FN;
        sW1t[i] = Wn1[(wo*FN + g)*F2 + k];
    }
    for (int i = threadIdx.x; i < FN*FN; i += blockDim.x) {
        const int k = i / FN, g = i % FN;
        sW2t[i] = Wn2[(wo*FN + g)*FN + k];
    }
    for (int i = threadIdx.x; i < FN; i += blockDim.x) {
        sb1[i] = bn1[wo*FN + i];
        sb2[i] = bn2[wo*FN + i];
    }
    __syncthreads();

    const int n0 = blockIdx.x*256 + threadIdx.x;
    if (n0 >= NN) return;
    const int n1r = n0 + 128;
    const bool v1 = (n1r < NN);
    const int n1 = v1 ? n1r : n0;

    const float4* x40 = (const float4*)(x      + (((size_t)p*NN + n0)*CC + c)*FF);
    const float4* a40 = (const float4*)(g_aggr + (((size_t)p*NN + n0)*CC + c)*FF);
    const float4* x41 = (const float4*)(x      + (((size_t)p*NN + n1)*CC + c)*FF);
    const float4* a41 = (const float4*)(g_aggr + (((size_t)p*NN + n1)*CC + c)*FF);

    // ---- layer 1 ----
    ull accA[32], accB[32];
    #pragma unroll
    for (int j = 0; j < 32; ++j) {
        PACK_F32X2(accA[j], sb1[2*j], sb1[2*j + 1]);
        accB[j] = accA[j];
    }

    #pragma unroll 1
    for (int fc = 0; fc < FF/4; ++fc) {
        const float4 u0 = x40[fc];
        const float4 u1 = x41[fc];
        const float* wk = sW1t + (4*fc)*FN;
        fma64_dual(accA, accB, wk + 0*FN, u0.x, u1.x);
        fma64_dual(accA, accB, wk + 1*FN, u0.y, u1.y);
        fma64_dual(accA, accB, wk + 2*FN, u0.z, u1.z);
        fma64_dual(accA, accB, wk + 3*FN, u0.w, u1.w);
    }
    #pragma unroll 1
    for (int fc = 0; fc < FF/4; ++fc) {
        const float4 u0 = a40[fc];
        const float4 u1 = a41[fc];
        const float* wk = sW1t + (FF + 4*fc)*FN;
        fma64_dual(accA, accB, wk + 0*FN, u0.x, u1.x);
        fma64_dual(accA, accB, wk + 1*FN, u0.y, u1.y);
        fma64_dual(accA, accB, wk + 2*FN, u0.z, u1.z);
        fma64_dual(accA, accB, wk + 3*FN, u0.w, u1.w);
    }

    float h0[FN], h1[FN];
    #pragma unroll
    for (int j = 0; j < 32; ++j) {
        float a0, a1; UNPACK_F32X2(a0, a1, accA[j]);
        h0[2*j] = tanhf(a0); h0[2*j+1] = tanhf(a1);
        UNPACK_F32X2(a0, a1, accB[j]);
        h1[2*j] = tanhf(a0); h1[2*j+1] = tanhf(a1);
    }

    // ---- layer 2 ----
    float* op0 = out + (((size_t)p*NN + n0)*CC + c)*FN;
    float* op1 = out + (((size_t)p*NN + n1)*CC + c)*FN;

    #pragma unroll 1
    for (int gb = 0; gb < 4; ++gb) {
        ull a0[8], a1[8];
        #pragma unroll
        for (int j = 0; j < 8; ++j) {
            PACK_F32X2(a0[j], sb2[gb*16 + 2*j], sb2[gb*16 + 2*j + 1]);
            a1[j] = a0[j];
        }
        #pragma unroll 4
        for (int k = 0; k < FN; ++k)
            fma16_dual(a0, a1, sW2t + k*FN + gb*16, h0[k], h1[k]);

        #pragma unroll
        for (int j = 0; j < 8; j += 2) {
            float q0, q1, q2, q3;
            UNPACK_F32X2(q0, q1, a0[j]);
            UNPACK_F32X2(q2, q3, a0[j+1]);
            *(float4*)(op0 + gb*16 + 2*j) =
                make_float4(tanhf(q0), tanhf(q1), tanhf(q2), tanhf(q3));
        }
        if (v1) {
            #pragma unroll
            for (int j = 0; j < 8; j += 2) {
                float q0, q1, q2, q3;
                UNPACK_F32X2(q0, q1, a1[j]);
                UNPACK_F32X2(q2, q3, a1[j+1]);
                *(float4*)(op1 + gb*16 + 2*j) =
                    make_float4(tanhf(q0), tanhf(q1), tanhf(q2), tanhf(q3));
            }
        }
    }
}

extern "C" void kernel_launch(void* const* d_in, const int* in_sizes, int n_in,
                              void* d_out, int out_size) {
    const float* x   = (const float*)d_in[0];
    const void*  ei  = d_in[1];
    const float* We1 = (const float*)d_in[2];
    const float* be1 = (const float*)d_in[3];
    const float* We2 = (const float*)d_in[4];
    const float* be2 = (const float*)d_in[5];
    const float* Wn1 = (const float*)d_in[6];
    const float* bn1 = (const float*)d_in[7];
    const float* Wn2 = (const float*)d_in[8];
    const float* bn2 = (const float*)d_in[9];
    float* out = (float*)d_out;

    const int smem_node = (F2*FN + FN*FN + 2*FN) * (int)sizeof(float);  // 51712 B
    cudaFuncSetAttribute(node_kernel,
                         cudaFuncAttributeMaxDynamicSharedMemorySize, smem_node);

    detect_kernel<<<1, 1>>>(ei);
    zero_kernel<<<1024, 256>>>();

    dim3 gp((NN*CC + 255)/256, PP);
    pre_kernel<<<gp, 256>>>(x, We1, be1);

    dim3 ge(EE/256, PP);
    edge_kernel<<<ge, 256>>>(x, ei, We2, be2);

    dim3 gn((NN + 255)/256, CC, PP);
    node_kernel<<<gn, 128, smem_node>>>(x, Wn1, bn1, Wn2, bn2, out);
}

// round 6
// speedup vs baseline: 1.0197x; 1.0197x over previous
#include <cuda_runtime.h>
#include <math.h>

#define PP 3
#define NN 50000
#define EE 256000
#define CC 5
#define FF 68
#define FE 16
#define FN 64
#define F2 (2*FF)   // 136

typedef unsigned long long ull;

#define PACK_F32X2(out, lo, hi) \
    asm("mov.b64 %0, {%1, %2};" : "=l"(out) : "f"(lo), "f"(hi))
#define UNPACK_F32X2(lo, hi, in) \
    asm("mov.b64 {%0, %1}, %2;" : "=f"(lo), "=f"(hi) : "l"(in))
#define FMA_F32X2(d, a, b, c) \
    asm("fma.rn.f32x2 %0, %1, %2, %3;" : "=l"(d) : "l"(a), "l"(b), "l"(c))

__device__ __forceinline__ float tanh_fast(float x) {
    float y; asm("tanh.approx.f32 %0, %1;" : "=f"(y) : "f"(x)); return y;
}

// Scratch: aggr [P,N,C,F] = 204 MB, A/B partials [P,N,C,16] = 48 MB each
__device__ __align__(16) float g_aggr[(size_t)PP*NN*CC*FF];
__device__ __align__(16) float g_A[(size_t)PP*NN*CC*FE];
__device__ __align__(16) float g_B[(size_t)PP*NN*CC*FE];
__device__ int g_is64;

__global__ void detect_kernel(const void* __restrict__ ei) {
    const long long* q = (const long long*)ei;
    int ok = 1;
    for (int i = 0; i < 64; ++i) {
        long long v = q[i];
        if (v < 0 || v >= NN) { ok = 0; break; }
    }
    g_is64 = ok;
}

__global__ void zero_kernel() {
    const size_t total = (size_t)PP*NN*CC*FF/4;
    float4* p = (float4*)g_aggr;
    const float4 z = make_float4(0.f, 0.f, 0.f, 0.f);
    for (size_t i = (size_t)blockIdx.x*blockDim.x + threadIdx.x; i < total;
         i += (size_t)gridDim.x*blockDim.x)
        p[i] = z;
}

__device__ __forceinline__ void red4(float* addr, float a, float b, float c, float d) {
    asm volatile("red.global.add.v4.f32 [%0], {%1,%2,%3,%4};"
                 :: "l"(addr), "f"(a), "f"(b), "f"(c), "f"(d) : "memory");
}

// 16 outputs (8 f32x2 acc) += u * w[0..15]
__device__ __forceinline__ void fma16(ull* acc2, const float* wk, float u) {
    ull uu; PACK_F32X2(uu, u, u);
    const ulonglong2* w = (const ulonglong2*)wk;
    #pragma unroll
    for (int j = 0; j < 4; ++j) {
        ulonglong2 wv = w[j];
        FMA_F32X2(acc2[2*j+0], uu, wv.x, acc2[2*j+0]);
        FMA_F32X2(acc2[2*j+1], uu, wv.y, acc2[2*j+1]);
    }
}

// ---------------------------------------------------------------------------
// Precompute kernel: per (node, class), A = W1a.x + b1 and B = W1b.x.
// ---------------------------------------------------------------------------
__global__ __launch_bounds__(256) void pre_kernel(
    const float* __restrict__ x,
    const float* __restrict__ We1, const float* __restrict__ be1)
{
    __shared__ __align__(16) float sW[CC*FF*32];  // 43.5 KB
    __shared__ float sb1[CC*FE];

    const int p = blockIdx.y;
    for (int i = threadIdx.x; i < CC*FF*32; i += blockDim.x) {
        const int c = i / (FF*32);
        const int r = i % (FF*32);
        const int k = r / 32;
        const int j = r % 32;
        const int g = (j < 16) ? j : j - 16;
        const int kk = (j < 16) ? k : FF + k;
        sW[i] = We1[(((size_t)p*CC + c)*FE + g)*F2 + kk];
    }
    for (int i = threadIdx.x; i < CC*FE; i += blockDim.x)
        sb1[i] = be1[p*CC*FE + i];
    __syncthreads();

    const int idx = blockIdx.x*blockDim.x + threadIdx.x;
    if (idx >= NN*CC) return;
    const int n = idx / CC;
    const int c = idx % CC;

    const float4* x4 = (const float4*)(x + (((size_t)p*NN + n)*CC + c)*FF);

    ull accA[8], accB[8];
    #pragma unroll
    for (int j = 0; j < 8; ++j) {
        PACK_F32X2(accA[j], sb1[c*FE + 2*j], sb1[c*FE + 2*j + 1]);
        float z = 0.f;
        PACK_F32X2(accB[j], z, z);
    }

    const float* wb = sW + c*FF*32;
    #pragma unroll 1
    for (int fc = 0; fc < FF/4; ++fc) {
        const float4 u = x4[fc];
        const float* wk = wb + (4*fc)*32;
        fma16(accA, wk + 0*32,      u.x); fma16(accB, wk + 0*32 + 16, u.x);
        fma16(accA, wk + 1*32,      u.y); fma16(accB, wk + 1*32 + 16, u.y);
        fma16(accA, wk + 2*32,      u.z); fma16(accB, wk + 2*32 + 16, u.z);
        fma16(accA, wk + 3*32,      u.w); fma16(accB, wk + 3*32 + 16, u.w);
    }

    float* Ao = g_A + (((size_t)p*NN + n)*CC + c)*FE;
    float* Bo = g_B + (((size_t)p*NN + n)*CC + c)*FE;
    #pragma unroll
    for (int j = 0; j < 8; j += 2) {
        float a0, a1, a2, a3, b0, b1, b2, b3;
        UNPACK_F32X2(a0, a1, accA[j]);
        UNPACK_F32X2(a2, a3, accA[j+1]);
        UNPACK_F32X2(b0, b1, accB[j]);
        UNPACK_F32X2(b2, b3, accB[j+1]);
        *(float4*)(Ao + 2*j) = make_float4(a0, a1, a2, a3);
        *(float4*)(Bo + 2*j) = make_float4(b0, b1, b2, b3);
    }
}

// ---------------------------------------------------------------------------
// Edge kernel: gather A[dst]+B[src], tanh-gate, class softmax, scatter w*x_j.
// ---------------------------------------------------------------------------
__global__ __launch_bounds__(256) void edge_kernel(
    const float* __restrict__ x, const void* __restrict__ ei,
    const float* __restrict__ We2, const float* __restrict__ be2)
{
    __shared__ float sW2[CC*FE];
    __shared__ float sb2[CC];

    const int p = blockIdx.y;
    for (int i = threadIdx.x; i < CC*FE; i += blockDim.x)
        sW2[i] = We2[p*CC*FE + i];
    if (threadIdx.x < CC) sb2[threadIdx.x] = be2[p*CC + threadIdx.x];
    __syncthreads();

    const int is64 = g_is64;
    const long long* ei64 = (const long long*)ei;
    const int*       ei32 = (const int*)ei;
    const size_t base = (size_t)p*2*EE;

    const int e = blockIdx.x*blockDim.x + threadIdx.x;   // EE % 256 == 0
    int s, d;
    if (is64) {
        s = (int)ei64[base + e];
        d = (int)ei64[base + EE + e];
    } else {
        s = ei32[base + e];
        d = ei32[base + EE + e];
    }

    const float4* Ad = (const float4*)(g_A + ((size_t)p*NN + d)*(CC*FE));
    const float4* Bs = (const float4*)(g_B + ((size_t)p*NN + s)*(CC*FE));

    float lg[CC];
    #pragma unroll
    for (int c = 0; c < CC; ++c) {
        float l = sb2[c];
        #pragma unroll
        for (int j = 0; j < 4; ++j) {
            const float4 a = Ad[c*4 + j];
            const float4 b = Bs[c*4 + j];
            l += tanh_fast(a.x + b.x) * sW2[c*FE + 4*j + 0]
               + tanh_fast(a.y + b.y) * sW2[c*FE + 4*j + 1]
               + tanh_fast(a.z + b.z) * sW2[c*FE + 4*j + 2]
               + tanh_fast(a.w + b.w) * sW2[c*FE + 4*j + 3];
        }
        lg[c] = l;
    }

    float mx = lg[0];
    #pragma unroll
    for (int c = 1; c < CC; ++c) mx = fmaxf(mx, lg[c]);
    float w[CC];
    float sum = 0.f;
    #pragma unroll
    for (int c = 0; c < CC; ++c) { w[c] = expf(lg[c] - mx); sum += w[c]; }
    const float inv = 1.f / sum;

    const float* xj = x + ((size_t)p*NN + s)*(CC*FF);
    float* ap = g_aggr + ((size_t)p*NN + d)*(CC*FF);
    #pragma unroll
    for (int c = 0; c < CC; ++c) {
        const float wc = w[c] * inv;
        const float4* mj = (const float4*)(xj + c*FF);
        float* a = ap + c*FF;
        #pragma unroll 1
        for (int fc = 0; fc < FF/4; ++fc) {
            const float4 v = mj[fc];
            red4(a + 4*fc, wc*v.x, wc*v.y, wc*v.z, wc*v.w);
        }
    }
}

// ---------------------------------------------------------------------------
// Node kernel v3: register-tiled GEMM. Block = 512 threads = 512 nodes of one
// (plane, class). Thread = 4 nodes x 16 outputs (g-quarter gq = tid&3).
// Per k: 4 LDS.128 weights + broadcast inputs feed 32 FFMA2 (1:8 ratio).
// Hidden h staged via smem [512][65] (pad 65 => conflict-free layer-2 reads).
// ---------------------------------------------------------------------------
#define NPB 512
#define HS  65

__global__ __launch_bounds__(512) void node_kernel(
    const float* __restrict__ x,
    const float* __restrict__ Wn1, const float* __restrict__ bn1,
    const float* __restrict__ Wn2, const float* __restrict__ bn2,
    float* __restrict__ out)
{
    extern __shared__ __align__(16) float sm[];
    float* sW1t = sm;                    // [136][64]
    float* sW2t = sW1t + F2*FN;          // [64][64]
    float* sb1  = sW2t + FN*FN;          // 64
    float* sb2  = sb1 + FN;              // 64
    float* hs   = sb2 + FN;              // [512][65]

    const int c = blockIdx.y;
    const int p = blockIdx.z;
    const size_t wo = (size_t)p*CC + c;
    for (int i = threadIdx.x; i < F2*FN; i += blockDim.x) {
        const int k = i >> 6, g = i & 63;
        sW1t[i] = Wn1[(wo*FN + g)*F2 + k];
    }
    for (int i = threadIdx.x; i < FN*FN; i += blockDim.x) {
        const int k = i >> 6, g = i & 63;
        sW2t[i] = Wn2[(wo*FN + g)*FN + k];
    }
    if (threadIdx.x < FN) {
        sb1[threadIdx.x] = bn1[wo*FN + threadIdx.x];
        sb2[threadIdx.x] = bn2[wo*FN + threadIdx.x];
    }
    __syncthreads();

    const int gq = threadIdx.x & 3;
    const int nl = threadIdx.x >> 2;          // 0..127 local node-quad
    const int n0 = blockIdx.x*NPB + nl*4;

    const int m0 = min(n0 + 0, NN - 1);
    const int m1 = min(n0 + 1, NN - 1);
    const int m2 = min(n0 + 2, NN - 1);
    const int m3 = min(n0 + 3, NN - 1);

    const float4* x40 = (const float4*)(x + (((size_t)p*NN + m0)*CC + c)*FF);
    const float4* x41 = (const float4*)(x + (((size_t)p*NN + m1)*CC + c)*FF);
    const float4* x42 = (const float4*)(x + (((size_t)p*NN + m2)*CC + c)*FF);
    const float4* x43 = (const float4*)(x + (((size_t)p*NN + m3)*CC + c)*FF);
    const float4* a40 = (const float4*)(g_aggr + (((size_t)p*NN + m0)*CC + c)*FF);
    const float4* a41 = (const float4*)(g_aggr + (((size_t)p*NN + m1)*CC + c)*FF);
    const float4* a42 = (const float4*)(g_aggr + (((size_t)p*NN + m2)*CC + c)*FF);
    const float4* a43 = (const float4*)(g_aggr + (((size_t)p*NN + m3)*CC + c)*FF);

    ull acc[4][8];
    #pragma unroll
    for (int j = 0; j < 8; ++j) {
        ull b; PACK_F32X2(b, sb1[gq*16 + 2*j], sb1[gq*16 + 2*j + 1]);
        acc[0][j] = b; acc[1][j] = b; acc[2][j] = b; acc[3][j] = b;
    }

#define K_STEP(S0, S1, S2, S3, WPTR)                                      \
    do {                                                                  \
        const ulonglong2* wq = (const ulonglong2*)(WPTR);                 \
        ulonglong2 w0 = wq[0], w1 = wq[1], w2 = wq[2], w3 = wq[3];        \
        ull uu;                                                           \
        PACK_F32X2(uu, S0, S0);                                           \
        FMA_F32X2(acc[0][0], uu, w0.x, acc[0][0]);                        \
        FMA_F32X2(acc[0][1], uu, w0.y, acc[0][1]);                        \
        FMA_F32X2(acc[0][2], uu, w1.x, acc[0][2]);                        \
        FMA_F32X2(acc[0][3], uu, w1.y, acc[0][3]);                        \
        FMA_F32X2(acc[0][4], uu, w2.x, acc[0][4]);                        \
        FMA_F32X2(acc[0][5], uu, w2.y, acc[0][5]);                        \
        FMA_F32X2(acc[0][6], uu, w3.x, acc[0][6]);                        \
        FMA_F32X2(acc[0][7], uu, w3.y, acc[0][7]);                        \
        PACK_F32X2(uu, S1, S1);                                           \
        FMA_F32X2(acc[1][0], uu, w0.x, acc[1][0]);                        \
        FMA_F32X2(acc[1][1], uu, w0.y, acc[1][1]);                        \
        FMA_F32X2(acc[1][2], uu, w1.x, acc[1][2]);                        \
        FMA_F32X2(acc[1][3], uu, w1.y, acc[1][3]);                        \
        FMA_F32X2(acc[1][4], uu, w2.x, acc[1][4]);                        \
        FMA_F32X2(acc[1][5], uu, w2.y, acc[1][5]);                        \
        FMA_F32X2(acc[1][6], uu, w3.x, acc[1][6]);                        \
        FMA_F32X2(acc[1][7], uu, w3.y, acc[1][7]);                        \
        PACK_F32X2(uu, S2, S2);                                           \
        FMA_F32X2(acc[2][0], uu, w0.x, acc[2][0]);                        \
        FMA_F32X2(acc[2][1], uu, w0.y, acc[2][1]);                        \
        FMA_F32X2(acc[2][2], uu, w1.x, acc[2][2]);                        \
        FMA_F32X2(acc[2][3], uu, w1.y, acc[2][3]);                        \
        FMA_F32X2(acc[2][4], uu, w2.x, acc[2][4]);                        \
        FMA_F32X2(acc[2][5], uu, w2.y, acc[2][5]);                        \
        FMA_F32X2(acc[2][6], uu, w3.x, acc[2][6]);                        \
        FMA_F32X2(acc[2][7], uu, w3.y, acc[2][7]);                        \
        PACK_F32X2(uu, S3, S3);                                           \
        FMA_F32X2(acc[3][0], uu, w0.x, acc[3][0]);                        \
        FMA_F32X2(acc[3][1], uu, w0.y, acc[3][1]);                        \
        FMA_F32X2(acc[3][2], uu, w1.x, acc[3][2]);                        \
        FMA_F32X2(acc[3][3], uu, w1.y, acc[3][3]);                        \
        FMA_F32X2(acc[3][4], uu, w2.x, acc[3][4]);                        \
        FMA_F32X2(acc[3][5], uu, w2.y, acc[3][5]);                        \
        FMA_F32X2(acc[3][6], uu, w3.x, acc[3][6]);                        \
        FMA_F32X2(acc[3][7], uu, w3.y, acc[3][7]);                        \
    } while (0)

    // ---- layer 1: x segment ----
    #pragma unroll 1
    for (int fc = 0; fc < FF/4; ++fc) {
        const float4 u0 = x40[fc], u1 = x41[fc], u2 = x42[fc], u3 = x43[fc];
        const float* wk = sW1t + (4*fc)*FN + gq*16;
        K_STEP(u0.x, u1.x, u2.x, u3.x, wk + 0*FN);
        K_STEP(u0.y, u1.y, u2.y, u3.y, wk + 1*FN);
        K_STEP(u0.z, u1.z, u2.z, u3.z, wk + 2*FN);
        K_STEP(u0.w, u1.w, u2.w, u3.w, wk + 3*FN);
    }
    // ---- layer 1: aggr segment ----
    #pragma unroll 1
    for (int fc = 0; fc < FF/4; ++fc) {
        const float4 u0 = a40[fc], u1 = a41[fc], u2 = a42[fc], u3 = a43[fc];
        const float* wk = sW1t + (FF + 4*fc)*FN + gq*16;
        K_STEP(u0.x, u1.x, u2.x, u3.x, wk + 0*FN);
        K_STEP(u0.y, u1.y, u2.y, u3.y, wk + 1*FN);
        K_STEP(u0.z, u1.z, u2.z, u3.z, wk + 2*FN);
        K_STEP(u0.w, u1.w, u2.w, u3.w, wk + 3*FN);
    }

    // h -> smem staging (tanh approx on hidden layer)
    #pragma unroll
    for (int j = 0; j < 4; ++j) {
        float* hrow = hs + (nl*4 + j)*HS + gq*16;
        #pragma unroll
        for (int q = 0; q < 8; ++q) {
            float a0, a1; UNPACK_F32X2(a0, a1, acc[j][q]);
            hrow[2*q]   = tanh_fast(a0);
            hrow[2*q+1] = tanh_fast(a1);
        }
    }
    __syncthreads();

    // ---- layer 2 ----
    #pragma unroll
    for (int j = 0; j < 8; ++j) {
        ull b; PACK_F32X2(b, sb2[gq*16 + 2*j], sb2[gq*16 + 2*j + 1]);
        acc[0][j] = b; acc[1][j] = b; acc[2][j] = b; acc[3][j] = b;
    }

    const float* h0 = hs + (nl*4 + 0)*HS;
    const float* h1 = hs + (nl*4 + 1)*HS;
    const float* h2 = hs + (nl*4 + 2)*HS;
    const float* h3 = hs + (nl*4 + 3)*HS;

    #pragma unroll 4
    for (int k = 0; k < FN; ++k) {
        const float* wk = sW2t + k*FN + gq*16;
        K_STEP(h0[k], h1[k], h2[k], h3[k], wk);
    }

    // ---- output (accurate tanh) ----
    #pragma unroll
    for (int j = 0; j < 4; ++j) {
        const int n = n0 + j;
        if (n >= NN) break;
        float* op = out + (((size_t)p*NN + n)*CC + c)*FN + gq*16;
        #pragma unroll
        for (int q = 0; q < 8; q += 2) {
            float a0, a1, b0, b1;
            UNPACK_F32X2(a0, a1, acc[j][q]);
            UNPACK_F32X2(b0, b1, acc[j][q+1]);
            *(float4*)(op + 2*q) =
                make_float4(tanhf(a0), tanhf(a1), tanhf(b0), tanhf(b1));
        }
    }
#undef K_STEP
}

extern "C" void kernel_launch(void* const* d_in, const int* in_sizes, int n_in,
                              void* d_out, int out_size) {
    const float* x   = (const float*)d_in[0];
    const void*  ei  = d_in[1];
    const float* We1 = (const float*)d_in[2];
    const float* be1 = (const float*)d_in[3];
    const float* We2 = (const float*)d_in[4];
    const float* be2 = (const float*)d_in[5];
    const float* Wn1 = (const float*)d_in[6];
    const float* bn1 = (const float*)d_in[7];
    const float* Wn2 = (const float*)d_in[8];
    const float* bn2 = (const float*)d_in[9];
    float* out = (float*)d_out;

    const int smem_node =
        (F2*FN + FN*FN + 2*FN + NPB*HS) * (int)sizeof(float);  // ~184 KB
    cudaFuncSetAttribute(node_kernel,
                         cudaFuncAttributeMaxDynamicSharedMemorySize, smem_node);

    detect_kernel<<<1, 1>>>(ei);
    zero_kernel<<<1024, 256>>>();

    dim3 gp((NN*CC + 255)/256, PP);
    pre_kernel<<<gp, 256>>>(x, We1, be1);

    dim3 ge(EE/256, PP);
    edge_kernel<<<ge, 256>>>(x, ei, We2, be2);

    dim3 gn((NN + NPB - 1)/NPB, CC, PP);
    node_kernel<<<gn, 512, smem_node>>>(x, Wn1, bn1, Wn2, bn2, out);
}